// round 14
// baseline (speedup 1.0000x reference)
#include <cuda_runtime.h>
#include <cstdint>
#include <math.h>

// ===== Problem dims =====
#define BB   16384
#define K1   784
#define HH   1024
#define NW   32          // HH/32 packed words per row
#define NOUT 10
#define NPART 128        // bgemm partial blocks (grid.y = BB/128)
#define NPART1 64        // gemm1 partial blocks (grid.y = BB/256)

#define BF16_P1 0x3F80u
#define BF16_M1 0xBF80u

// ===== Scratch (device globals) =====
__device__ float    g_h[(size_t)BB*HH];
__device__ unsigned g_nv[BB*NW];
__device__ unsigned g_act[BB*NW];            // packed bits (k_out)
__device__ unsigned short g_actb[(size_t)BB*HH];   // bf16 +-1 activations
__device__ float    g_sW1[K1*HH];            // sign(W1)^T, [k][n]
__device__ unsigned g_w2[HH*NW];
__device__ unsigned g_w3[HH*NW];
__device__ unsigned g_w4[NOUT*NW];
__device__ unsigned short g_w2b[HH*HH];      // bf16 +-1 weights [n][k]
__device__ unsigned short g_w3b[HH*HH];
__device__ double   g_part[NPART][2*HH];
__device__ float    g_muf[HH];
__device__ float    g_rf[HH];
__device__ unsigned g_sel[NW];
__device__ unsigned g_mb[NW];
__device__ float    g_lutf[27];

// ---- helpers ----
__device__ __forceinline__ unsigned long long fma2(unsigned long long a,
                                                   unsigned long long b,
                                                   unsigned long long c) {
    unsigned long long d;
    asm("fma.rn.f32x2 %0, %1, %2, %3;" : "=l"(d) : "l"(a), "l"(b), "l"(c));
    return d;
}
__device__ __forceinline__ unsigned long long dup2(float a) {
    unsigned long long d;
    asm("mov.b64 %0, {%1, %1};" : "=l"(d) : "r"(__float_as_uint(a)));
    return d;
}
__device__ __forceinline__ void kadd(float v, float& s, float& c) {
    float y = __fsub_rn(v, c);
    float t = __fadd_rn(s, y);
    c = __fsub_rn(__fsub_rn(t, s), y);
    s = t;
}
__device__ __forceinline__ unsigned smem_u32(const void* p) {
    unsigned a;
    asm("{ .reg .u64 t; cvta.to.shared.u64 t, %1; cvt.u32.u64 %0, t; }" : "=r"(a) : "l"(p));
    return a;
}
__device__ __forceinline__ void ldm_x4(unsigned& d0, unsigned& d1, unsigned& d2, unsigned& d3,
                                       unsigned addr) {
    asm volatile("ldmatrix.sync.aligned.m8n8.x4.shared.b16 {%0,%1,%2,%3}, [%4];"
                 : "=r"(d0), "=r"(d1), "=r"(d2), "=r"(d3) : "r"(addr));
}
__device__ __forceinline__ void mma16816(float& c0, float& c1, float& c2, float& c3,
                                         unsigned a0, unsigned a1, unsigned a2, unsigned a3,
                                         unsigned b0, unsigned b1) {
    asm volatile("mma.sync.aligned.m16n8k16.row.col.f32.bf16.bf16.f32 "
                 "{%0,%1,%2,%3}, {%4,%5,%6,%7}, {%8,%9}, {%0,%1,%2,%3};"
                 : "+f"(c0), "+f"(c1), "+f"(c2), "+f"(c3)
                 : "r"(a0), "r"(a1), "r"(a2), "r"(a3), "r"(b0), "r"(b1));
}

// ===================================================================
// Flip-threshold LUT (exact vs fp64 path; see R4 derivation)
// ===================================================================
__global__ void k_mklut() {
    int m = threadIdx.x;          // 0..26
    float t;
    if (m <= 25) {
        float x = (float)(2 * m);
        float q2 = (x * x) / 50.0f;
        double prob = 0.5 * exp(-(double)q2);
        t = (float)prob;
        if ((double)t < prob) t = __int_as_float(__float_as_int(t) + 1);
    } else t = -1.0f;
    g_lutf[m] = t;
}

// sign(W1)^T via smem tile transpose
__global__ void k_signW1(const float* __restrict__ W1) {
    __shared__ float tile[32][33];
    int k0 = blockIdx.x * 32, n0 = blockIdx.y * 32;
    int tx = threadIdx.x, ty = threadIdx.y;      // (32, 8)
#pragma unroll
    for (int r = 0; r < 32; r += 8) {
        int n = n0 + ty + r, k = k0 + tx;
        float w = (k < K1) ? W1[(size_t)n * K1 + k] : 0.f;
        tile[ty + r][tx] = (w > 0.f) ? 1.f : ((w < 0.f) ? -1.f : 0.f);
    }
    __syncthreads();
#pragma unroll
    for (int r = 0; r < 32; r += 8) {
        int k = k0 + ty + r, n = n0 + tx;
        if (k < K1) g_sW1[(size_t)k * HH + n] = tile[tx][ty + r];
    }
}

// Packs W2, W3, W4 sign bits; also emits bf16 +-1 copies of W2/W3.
#define W2_ELEMS (HH*HH)
#define W4_ELEMS (NOUT*HH)
__global__ void k_packAll(const float* __restrict__ W2,
                          const float* __restrict__ W3,
                          const float* __restrict__ W4) {
    int idx = blockIdx.x * 256 + threadIdx.x;
    const float* W; unsigned* dst; unsigned short* dstb; int off;
    if (idx < W2_ELEMS)               { W = W2; dst = g_w2; dstb = g_w2b; off = 0; }
    else if (idx < 2 * W2_ELEMS)      { W = W3; dst = g_w3; dstb = g_w3b; off = W2_ELEMS; }
    else                              { W = W4; dst = g_w4; dstb = 0;     off = 2 * W2_ELEMS; }
    int li = idx - off;
    bool in = (idx < 2 * W2_ELEMS + W4_ELEMS);
    bool pos = in ? (W[li] > 0.f) : false;
    unsigned bal = __ballot_sync(0xffffffffu, pos);
    if ((threadIdx.x & 31) == 0 && in) dst[li >> 5] = bal;
    if (in && dstb) dstb[li] = pos ? (unsigned short)BF16_P1 : (unsigned short)BF16_M1;
}

// ===================================================================
// Layer 1 SGEMM: R9/R13 configuration (best measured). UNCHANGED.
// ===================================================================
__global__ __launch_bounds__(256, 1) void k_gemm1(const float* __restrict__ X) {
    __shared__ union {
        struct { float As[2][16][256]; float Bs[2][16][128]; } g;   // 48 KB
        struct { float s[16][128]; float c[16][128];
                 float q[16][128]; float cq[16][128]; } st;         // 32 KB
    } sm;
    int bn0 = blockIdx.x * 128;
    int bm0 = blockIdx.y * 256;
    int tid = threadIdx.x;
    int ty = tid >> 4, tx = tid & 15;

    const float* aptr = &X[(size_t)(bm0 + tid) * K1];
    const float* bptr = &g_sW1[(size_t)ty * HH + bn0 + tx * 8];

    unsigned long long acc2[16][4];
#pragma unroll
    for (int i = 0; i < 16; i++)
#pragma unroll
        for (int q = 0; q < 4; q++) acc2[i][q] = 0ULL;

    float4 av[4], bv0, bv1;
#pragma unroll
    for (int i = 0; i < 4; i++) av[i] = *(const float4*)(aptr + 4 * i);
    bv0 = *(const float4*)bptr;
    bv1 = *(const float4*)(bptr + 4);
    {
#pragma unroll
        for (int i = 0; i < 4; i++) {
            sm.g.As[0][4*i + 0][tid] = av[i].x;
            sm.g.As[0][4*i + 1][tid] = av[i].y;
            sm.g.As[0][4*i + 2][tid] = av[i].z;
            sm.g.As[0][4*i + 3][tid] = av[i].w;
        }
        *(float4*)&sm.g.Bs[0][ty][tx * 8]     = bv0;
        *(float4*)&sm.g.Bs[0][ty][tx * 8 + 4] = bv1;
    }
    __syncthreads();

    int buf = 0;
    for (int kt = 16; kt <= K1; kt += 16) {
        bool more = (kt < K1);
        if (more) {
#pragma unroll
            for (int i = 0; i < 4; i++) av[i] = *(const float4*)(aptr + kt + 4 * i);
            bv0 = *(const float4*)(bptr + (size_t)kt * HH);
            bv1 = *(const float4*)(bptr + (size_t)kt * HH + 4);
        }
#pragma unroll
        for (int k = 0; k < 16; k++) {
            float4 a0 = *(const float4*)&sm.g.As[buf][k][ty * 16];
            float4 a1 = *(const float4*)&sm.g.As[buf][k][ty * 16 + 4];
            float4 a2 = *(const float4*)&sm.g.As[buf][k][ty * 16 + 8];
            float4 a3 = *(const float4*)&sm.g.As[buf][k][ty * 16 + 12];
            ulonglong2 b01 = *(const ulonglong2*)&sm.g.Bs[buf][k][tx * 8];
            ulonglong2 b23 = *(const ulonglong2*)&sm.g.Bs[buf][k][tx * 8 + 4];
            unsigned long long bq[4] = {b01.x, b01.y, b23.x, b23.y};
            float a[16] = {a0.x, a0.y, a0.z, a0.w, a1.x, a1.y, a1.z, a1.w,
                           a2.x, a2.y, a2.z, a2.w, a3.x, a3.y, a3.z, a3.w};
#pragma unroll
            for (int i = 0; i < 16; i++) {
                unsigned long long ai = dup2(a[i]);
#pragma unroll
                for (int q = 0; q < 4; q++)
                    acc2[i][q] = fma2(ai, bq[q], acc2[i][q]);
            }
        }
        if (more) {
            int nb = buf ^ 1;
#pragma unroll
            for (int i = 0; i < 4; i++) {
                sm.g.As[nb][4*i + 0][tid] = av[i].x;
                sm.g.As[nb][4*i + 1][tid] = av[i].y;
                sm.g.As[nb][4*i + 2][tid] = av[i].z;
                sm.g.As[nb][4*i + 3][tid] = av[i].w;
            }
            *(float4*)&sm.g.Bs[nb][ty][tx * 8]     = bv0;
            *(float4*)&sm.g.Bs[nb][ty][tx * 8 + 4] = bv1;
            __syncthreads();
            buf = nb;
        }
    }

    float ss[8] = {0,0,0,0,0,0,0,0}, sc[8] = {0,0,0,0,0,0,0,0};
    float qs[8] = {0,0,0,0,0,0,0,0}, qc[8] = {0,0,0,0,0,0,0,0};
#pragma unroll
    for (int i = 0; i < 16; i++) {
        unsigned long long* p =
            (unsigned long long*)&g_h[(size_t)(bm0 + ty * 16 + i) * HH + bn0 + tx * 8];
        *(ulonglong2*)p       = make_ulonglong2(acc2[i][0], acc2[i][1]);
        *(ulonglong2*)(p + 2) = make_ulonglong2(acc2[i][2], acc2[i][3]);
#pragma unroll
        for (int q = 0; q < 4; q++) {
            float2 v2 = *(float2*)&acc2[i][q];
            kadd(v2.x, ss[2*q],   sc[2*q]);
            kadd(__fmul_rn(v2.x, v2.x), qs[2*q],   qc[2*q]);
            kadd(v2.y, ss[2*q+1], sc[2*q+1]);
            kadd(__fmul_rn(v2.y, v2.y), qs[2*q+1], qc[2*q+1]);
        }
    }
    __syncthreads();
#pragma unroll
    for (int j = 0; j < 8; j++) {
        int col = tx * 8 + j;
        sm.st.s[ty][col]  = ss[j];
        sm.st.c[ty][col]  = sc[j];
        sm.st.q[ty][col]  = qs[j];
        sm.st.cq[ty][col] = qc[j];
    }
    __syncthreads();
    if (tid < 128) {
        double sd = 0, qd = 0;
#pragma unroll
        for (int t = 0; t < 16; t++) {
            sd += (double)sm.st.s[t][tid] - (double)sm.st.c[t][tid];
            qd += (double)sm.st.q[t][tid] - (double)sm.st.cq[t][tid];
        }
        g_part[blockIdx.y][bn0 + tid]      = sd;
        g_part[blockIdx.y][HH + bn0 + tid] = qd;
    }
}

__global__ void k_reduce1() {
    int c = blockIdx.x * 256 + threadIdx.x;
    double s = 0, sq = 0;
    for (int p = 0; p < NPART1; p++) { s += g_part[p][c]; sq += g_part[p][HH + c]; }
    double mu = s / (double)BB;
    double var = sq / (double)BB - mu * mu;
    g_muf[c] = (float)mu;
    g_rf[c]  = (float)(1.0 / sqrt(var + 1e-5));
}

// Pack sign(BN(h1)) -> bits (for word path) AND bf16 +-1 (for mma path)
__global__ void k_pack1(const float* __restrict__ gv, const float* __restrict__ bv) {
    int idx = blockIdx.x * 256 + threadIdx.x;
    int c = idx & (HH - 1);
    float h = g_h[idx];
    float z = __fadd_rn(__fmul_rn(__fmul_rn(__fsub_rn(h, g_muf[c]), g_rf[c]), gv[c]), bv[c]);
    bool pos = (z > 0.f);
    unsigned bal = __ballot_sync(0xffffffffu, pos);
    if ((threadIdx.x & 31) == 0) g_act[idx >> 5] = bal;
    g_actb[idx] = pos ? (unsigned short)BF16_P1 : (unsigned short)BF16_M1;
}

// ===================================================================
// Binary GEMM via bf16 HMMA (exact: +-1 products, int sums <= 1024 in f32)
// CTA 128x128, 256 thr, 8 warps (2 m x 4 n), warp tile 64x32.
// BK=32, double-buffered smem, ldmatrix feeds, pitch 40 (conflict-free).
// Epilogue: h staged to smem s16, then the PROVEN noisy/pack/csum code.
// ===================================================================
#define APITCH 40
#define HP 136
__global__ __launch_bounds__(256) void k_bgemm_mma(int which, const float* __restrict__ U) {
    __shared__ union {
        struct { unsigned short A[2][128 * APITCH];
                 unsigned short B[2][128 * APITCH]; } stg;               // 40960 B
        struct { short Hs[128 * HP];
                 unsigned char sbits[128][16];
                 int icol[128][17]; } epi;                               // 45568 B
    } sm;
    __shared__ float lut[27];

    const unsigned short* __restrict__ Wb = (which == 0) ? g_w2b : g_w3b;
    int bn0 = blockIdx.x * 128;
    int bm0 = blockIdx.y * 128;
    int tid = threadIdx.x;
    int w = tid >> 5, lane = tid & 31;
    int warp_m = w >> 2, warp_n = w & 3;

    if (tid < 27) lut[tid] = g_lutf[tid];

    // loader: thread covers row tid/2, k-half (tid&1)*16 (32B = 2 uint4)
    int lrow = tid >> 1, lk = (tid & 1) * 16;
    const uint4* gA = (const uint4*)(g_actb + (size_t)(bm0 + lrow) * HH + lk);
    const uint4* gB = (const uint4*)(Wb     + (size_t)(bn0 + lrow) * HH + lk);
    unsigned sAbase = smem_u32(&sm.stg.A[0][0]);
    unsigned sBbase = smem_u32(&sm.stg.B[0][0]);
    unsigned sOff = (unsigned)(lrow * APITCH + lk) * 2;   // bytes

    float c[4][4][4];
#pragma unroll
    for (int mf = 0; mf < 4; mf++)
#pragma unroll
        for (int nf = 0; nf < 4; nf++)
#pragma unroll
            for (int v = 0; v < 4; v++) c[mf][nf][v] = 0.f;

    // ldmatrix per-thread address offsets (elements)
    int aRow = warp_m * 64 + (lane & 15);            // + mf*16
    int aKof = 8 * (lane >> 4);                      // + ks
    int bRow = warp_n * 32 + (lane & 7) + 8 * (lane >> 4);   // + p*16
    int bKof = 8 * ((lane >> 3) & 1);                // + ks

    // prologue: chunk 0
    uint4 ra0 = gA[0], ra1 = gA[1], rb0 = gB[0], rb1 = gB[1];
    *(uint4*)(sm.stg.A[0] + lrow * APITCH + lk)     = ra0;
    *(uint4*)(sm.stg.A[0] + lrow * APITCH + lk + 8) = ra1;
    *(uint4*)(sm.stg.B[0] + lrow * APITCH + lk)     = rb0;
    *(uint4*)(sm.stg.B[0] + lrow * APITCH + lk + 8) = rb1;
    __syncthreads();

    int buf = 0;
    for (int ch = 0; ch < 32; ch++) {
        bool more = (ch < 31);
        if (more) {
            const uint4* pA = (const uint4*)(g_actb + (size_t)(bm0 + lrow) * HH + (ch + 1) * 32 + lk);
            const uint4* pB = (const uint4*)(Wb     + (size_t)(bn0 + lrow) * HH + (ch + 1) * 32 + lk);
            ra0 = pA[0]; ra1 = pA[1]; rb0 = pB[0]; rb1 = pB[1];
        }
        unsigned aB = sAbase + (unsigned)(buf * 128 * APITCH) * 2;
        unsigned bB = sBbase + (unsigned)(buf * 128 * APITCH) * 2;
#pragma unroll
        for (int ks = 0; ks < 32; ks += 16) {
            unsigned af[4][4];
#pragma unroll
            for (int mf = 0; mf < 4; mf++)
                ldm_x4(af[mf][0], af[mf][1], af[mf][2], af[mf][3],
                       aB + (unsigned)((aRow + mf * 16) * APITCH + ks + aKof) * 2);
            unsigned bf[4][2];
#pragma unroll
            for (int p = 0; p < 2; p++)
                ldm_x4(bf[2*p][0], bf[2*p][1], bf[2*p+1][0], bf[2*p+1][1],
                       bB + (unsigned)((bRow + p * 16) * APITCH + ks + bKof) * 2);
#pragma unroll
            for (int mf = 0; mf < 4; mf++)
#pragma unroll
                for (int nf = 0; nf < 4; nf++)
                    mma16816(c[mf][nf][0], c[mf][nf][1], c[mf][nf][2], c[mf][nf][3],
                             af[mf][0], af[mf][1], af[mf][2], af[mf][3],
                             bf[nf][0], bf[nf][1]);
        }
        if (more) {
            int nb = buf ^ 1;
            *(uint4*)(sm.stg.A[nb] + lrow * APITCH + lk)     = ra0;
            *(uint4*)(sm.stg.A[nb] + lrow * APITCH + lk + 8) = ra1;
            *(uint4*)(sm.stg.B[nb] + lrow * APITCH + lk)     = rb0;
            *(uint4*)(sm.stg.B[nb] + lrow * APITCH + lk + 8) = rb1;
        }
        __syncthreads();
        buf ^= 1;
    }

    // Stage h (exact integers) into smem s16 pairs
#pragma unroll
    for (int mf = 0; mf < 4; mf++) {
#pragma unroll
        for (int nf = 0; nf < 4; nf++) {
            int col = warp_n * 32 + nf * 8 + 2 * (lane & 3);
            int r0 = warp_m * 64 + mf * 16 + (lane >> 2);
            unsigned v0 = ((unsigned)(unsigned short)(short)(int)c[mf][nf][0]) |
                          (((unsigned)(unsigned short)(short)(int)c[mf][nf][1]) << 16);
            unsigned v1 = ((unsigned)(unsigned short)(short)(int)c[mf][nf][2]) |
                          (((unsigned)(unsigned short)(short)(int)c[mf][nf][3]) << 16);
            ((unsigned*)sm.epi.Hs)[(r0 * HP + col) >> 1]       = v0;
            ((unsigned*)sm.epi.Hs)[((r0 + 8) * HP + col) >> 1] = v1;
        }
    }
    __syncthreads();

    // ==== PROVEN epilogue (from k_bgemm_fused), h read from smem ====
    int ty = tid >> 4, tx = tid & 15;
    int csum[8];
#pragma unroll
    for (int j = 0; j < 8; j++) csum[j] = 0;
#pragma unroll
    for (int i = 0; i < 8; i++) {
        int row = ty * 8 + i;
        int rowg = bm0 + row;
        float4 u0 = *(const float4*)&U[(size_t)rowg * HH + bn0 + tx * 8];
        float4 u1 = *(const float4*)&U[(size_t)rowg * HH + bn0 + tx * 8 + 4];
        float uu[8] = {u0.x, u0.y, u0.z, u0.w, u1.x, u1.y, u1.z, u1.w};
        unsigned byte = 0;
#pragma unroll
        for (int jp = 0; jp < 4; jp++) {
            unsigned v = ((unsigned*)sm.epi.Hs)[(row * HP + tx * 8 + 2 * jp) >> 1];
            int h0 = (int)(short)(v & 0xFFFF);
            int h1 = (int)(short)(v >> 16);
#pragma unroll
            for (int e = 0; e < 2; e++) {
                int hh = e ? h1 : h0;
                int hs = hh >> 1;
                int m = (hs < 0) ? -hs : hs;
                if (m > 26) m = 26;
                bool pos = (hs > 0) ^ (uu[2 * jp + e] < lut[m]);
                byte |= (pos ? 1u : 0u) << (2 * jp + e);
                csum[2 * jp + e] += pos ? 1 : -1;
            }
        }
        sm.epi.sbits[row][tx] = (unsigned char)byte;
    }
#pragma unroll
    for (int j = 0; j < 8; j++) sm.epi.icol[tx * 8 + j][ty] = csum[j];
    __syncthreads();

#pragma unroll
    for (int v = 0; v < 2; v++) {
        int wi = tid * 2 + v;
        int row = wi >> 2, wd = wi & 3;
        unsigned word = *(const unsigned*)&sm.epi.sbits[row][wd * 4];
        g_nv[(size_t)(bm0 + row) * NW + blockIdx.x * 4 + wd] = word;
    }
    if (tid < 128) {
        int s = 0;
#pragma unroll
        for (int t = 0; t < 16; t++) s += sm.epi.icol[tid][t];
        g_part[blockIdx.y][bn0 + tid] = (double)s;
    }
}

__global__ void k_lut(const float* __restrict__ gv, const float* __restrict__ bv) {
    int c = threadIdx.x;        // 1024 threads
    double s = 0;
    for (int p = 0; p < NPART; p++) s += g_part[p][c];
    double mu = s / (double)BB;
    double r = 1.0 / sqrt(1.0 - mu * mu + 1e-5);
    double zp = (( 1.0 - mu) * r) * (double)gv[c] + (double)bv[c];
    double zm = ((-1.0 - mu) * r) * (double)gv[c] + (double)bv[c];
    unsigned pb = __ballot_sync(0xffffffffu, zp > 0.0);
    unsigned mb = __ballot_sync(0xffffffffu, zm > 0.0);
    if ((c & 31) == 0) {
        g_sel[c >> 5] = pb ^ mb;
        g_mb[c >> 5]  = mb;
    }
}

// apply BN-LUT to nv bits -> packed act AND bf16 act
__global__ void k_apply() {
    int i = blockIdx.x * 256 + threadIdx.x;   // word index
    int wd = i & (NW - 1);
    unsigned word = (g_nv[i] & g_sel[wd]) ^ g_mb[wd];
    g_act[i] = word;
    unsigned short* dst = g_actb + (size_t)i * 32;
#pragma unroll
    for (int b = 0; b < 32; b += 2) {
        unsigned lo = (word >> b) & 1u, hi = (word >> (b + 1)) & 1u;
        unsigned v = (lo ? BF16_P1 : BF16_M1) | ((hi ? BF16_P1 : BF16_M1) << 16);
        *(unsigned*)(dst + b) = v;
    }
}

__global__ __launch_bounds__(256) void k_out(float* __restrict__ outp) {
    __shared__ unsigned As[256][33];
    __shared__ unsigned W4s[NOUT][NW];
    int r0 = blockIdx.x * 256;
    int t = threadIdx.x;
#pragma unroll
    for (int i = 0; i < 32; i++) {
        int p = t + 256 * i;
        As[p >> 5][p & 31] = g_act[(size_t)r0 * NW + p];
    }
    for (int i = t; i < NOUT * NW; i += 256) ((unsigned*)W4s)[i] = g_w4[i];
    __syncthreads();
#pragma unroll
    for (int o = 0; o < NOUT; o++) {
        int cnt = 0;
#pragma unroll
        for (int w = 0; w < NW; w += 2)
            cnt += __popc(As[t][w] ^ W4s[o][w]) + __popc(As[t][w + 1] ^ W4s[o][w + 1]);
        outp[(size_t)(r0 + t) * NOUT + o] = (float)(HH - 2 * cnt);
    }
}

// ===================================================================
extern "C" void kernel_launch(void* const* d_in, const int* in_sizes, int n_in,
                              void* d_out, int out_size) {
    const float* x  = (const float*)d_in[0];
    const float* u2 = (const float*)d_in[1];
    const float* u3 = (const float*)d_in[2];
    const float* W1 = (const float*)d_in[3];
    const float* W2 = (const float*)d_in[4];
    const float* W3 = (const float*)d_in[5];
    const float* W4 = (const float*)d_in[6];
    const float* g1 = (const float*)d_in[7];
    const float* b1 = (const float*)d_in[8];
    const float* g2 = (const float*)d_in[9];
    const float* b2 = (const float*)d_in[10];
    const float* g3 = (const float*)d_in[11];
    const float* b3 = (const float*)d_in[12];
    float* out = (float*)d_out;

    k_mklut<<<1, 27>>>();
    {
        dim3 tb(32, 8), tg((K1 + 31) / 32, HH / 32);
        k_signW1<<<tg, tb>>>(W1);
    }
    k_packAll<<<(2 * W2_ELEMS + W4_ELEMS + 255) / 256, 256>>>(W2, W3, W4);

    // Layer 1 (unchanged R13 config)
    dim3 g1grid(HH / 128, BB / 256);
    k_gemm1<<<g1grid, 256>>>(x);
    k_reduce1<<<HH / 256, 256>>>();
    k_pack1<<<(BB * HH) / 256, 256>>>(g1, b1);

    dim3 ggrid(HH / 128, BB / 128);
    // Layer 2 (tensor-core bgemm)
    k_bgemm_mma<<<ggrid, 256>>>(0, u2);
    k_lut<<<1, HH>>>(g2, b2);
    k_apply<<<(BB * NW) / 256, 256>>>();

    // Layer 3
    k_bgemm_mma<<<ggrid, 256>>>(1, u3);
    k_lut<<<1, HH>>>(g3, b3);
    k_apply<<<(BB * NW) / 256, 256>>>();

    // Output layer
    k_out<<<BB / 256, 256>>>(out);
}

// round 15
// speedup vs baseline: 1.1735x; 1.1735x over previous
#include <cuda_runtime.h>
#include <cstdint>
#include <math.h>

// ===== Problem dims =====
#define BB   16384
#define K1   784
#define HH   1024
#define NW   32          // HH/32 packed words per row
#define NOUT 10
#define NPART 128        // bgemm partial blocks (grid.y = BB/128)
#define NPART1 64        // gemm1 partial blocks (grid.y = BB/256)

// ===== Scratch (device globals) =====
__device__ float    g_h[(size_t)BB*HH];
__device__ unsigned g_nv[BB*NW];
__device__ unsigned g_act[BB*NW];
__device__ float    g_sW1[K1*HH];           // sign(W1)^T, [k][n]
__device__ unsigned g_w2[HH*NW];
__device__ unsigned g_w3[HH*NW];
__device__ unsigned g_w4[NOUT*NW];
__device__ double   g_part[NPART][2*HH];
__device__ float    g_muf[HH];
__device__ float    g_rf[HH];
__device__ unsigned g_sel[NW];
__device__ unsigned g_mb[NW];
__device__ float    g_lutf[27];

// packed f32x2 fma: halves round independently (rn) -> each half's chain
// is bit-identical to scalar FFMA in the same order.
__device__ __forceinline__ unsigned long long fma2(unsigned long long a,
                                                   unsigned long long b,
                                                   unsigned long long c) {
    unsigned long long d;
    asm("fma.rn.f32x2 %0, %1, %2, %3;" : "=l"(d) : "l"(a), "l"(b), "l"(c));
    return d;
}
__device__ __forceinline__ unsigned long long dup2(float a) {
    unsigned long long d;
    asm("mov.b64 %0, {%1, %1};" : "=l"(d) : "r"(__float_as_uint(a)));
    return d;
}
__device__ __forceinline__ void kadd(float v, float& s, float& c) {
    float y = __fsub_rn(v, c);
    float t = __fadd_rn(s, y);
    c = __fsub_rn(__fsub_rn(t, s), y);
    s = t;
}

// ===================================================================
// Flip-threshold LUT (exact vs fp64 path; see R4 derivation)
// ===================================================================
__global__ void k_mklut() {
    int m = threadIdx.x;          // 0..26
    float t;
    if (m <= 25) {
        float x = (float)(2 * m);
        float q2 = (x * x) / 50.0f;
        double prob = 0.5 * exp(-(double)q2);
        t = (float)prob;
        if ((double)t < prob) t = __int_as_float(__float_as_int(t) + 1);
    } else t = -1.0f;
    g_lutf[m] = t;
}

// sign(W1)^T via smem tile transpose
__global__ void k_signW1(const float* __restrict__ W1) {
    __shared__ float tile[32][33];
    int k0 = blockIdx.x * 32, n0 = blockIdx.y * 32;
    int tx = threadIdx.x, ty = threadIdx.y;      // (32, 8)
#pragma unroll
    for (int r = 0; r < 32; r += 8) {
        int n = n0 + ty + r, k = k0 + tx;
        float w = (k < K1) ? W1[(size_t)n * K1 + k] : 0.f;
        tile[ty + r][tx] = (w > 0.f) ? 1.f : ((w < 0.f) ? -1.f : 0.f);
    }
    __syncthreads();
#pragma unroll
    for (int r = 0; r < 32; r += 8) {
        int k = k0 + ty + r, n = n0 + tx;
        if (k < K1) g_sW1[(size_t)k * HH + n] = tile[tx][ty + r];
    }
}

// Single kernel packs W2, W3, W4 sign bits
#define W2_ELEMS (HH*HH)
#define W4_ELEMS (NOUT*HH)
__global__ void k_packAll(const float* __restrict__ W2,
                          const float* __restrict__ W3,
                          const float* __restrict__ W4) {
    int idx = blockIdx.x * 256 + threadIdx.x;
    const float* W; unsigned* dst; int off;
    if (idx < W2_ELEMS)               { W = W2; dst = g_w2; off = 0; }
    else if (idx < 2 * W2_ELEMS)      { W = W3; dst = g_w3; off = W2_ELEMS; }
    else                              { W = W4; dst = g_w4; off = 2 * W2_ELEMS; }
    int li = idx - off;
    bool pos = (idx < 2 * W2_ELEMS + W4_ELEMS) ? (W[li] > 0.f) : false;
    unsigned bal = __ballot_sync(0xffffffffu, pos);
    if ((threadIdx.x & 31) == 0 && idx < 2 * W2_ELEMS + W4_ELEMS) dst[li >> 5] = bal;
}

// ===================================================================
// Layer 1 SGEMM: R9/R13 configuration (best measured: ~619us plateau).
// 256x128 CTA tile, 256 threads, 16x8 per thread, BK=16, double-buffered
// f32x2. Per-output chain: one accumulator, k ascending -> bit-identical.
// Fused BN1 stats epilogue. DO NOT change geometry (R11/R12 regressed).
// ===================================================================
__global__ __launch_bounds__(256, 1) void k_gemm1(const float* __restrict__ X) {
    __shared__ union {
        struct { float As[2][16][256]; float Bs[2][16][128]; } g;   // 48 KB
        struct { float s[16][128]; float c[16][128];
                 float q[16][128]; float cq[16][128]; } st;         // 32 KB
    } sm;
    int bn0 = blockIdx.x * 128;
    int bm0 = blockIdx.y * 256;
    int tid = threadIdx.x;
    int ty = tid >> 4, tx = tid & 15;

    const float* aptr = &X[(size_t)(bm0 + tid) * K1];
    const float* bptr = &g_sW1[(size_t)ty * HH + bn0 + tx * 8];

    unsigned long long acc2[16][4];
#pragma unroll
    for (int i = 0; i < 16; i++)
#pragma unroll
        for (int q = 0; q < 4; q++) acc2[i][q] = 0ULL;

    float4 av[4], bv0, bv1;
#pragma unroll
    for (int i = 0; i < 4; i++) av[i] = *(const float4*)(aptr + 4 * i);
    bv0 = *(const float4*)bptr;
    bv1 = *(const float4*)(bptr + 4);
    {
#pragma unroll
        for (int i = 0; i < 4; i++) {
            sm.g.As[0][4*i + 0][tid] = av[i].x;
            sm.g.As[0][4*i + 1][tid] = av[i].y;
            sm.g.As[0][4*i + 2][tid] = av[i].z;
            sm.g.As[0][4*i + 3][tid] = av[i].w;
        }
        *(float4*)&sm.g.Bs[0][ty][tx * 8]     = bv0;
        *(float4*)&sm.g.Bs[0][ty][tx * 8 + 4] = bv1;
    }
    __syncthreads();

    int buf = 0;
    for (int kt = 16; kt <= K1; kt += 16) {
        bool more = (kt < K1);
        if (more) {
#pragma unroll
            for (int i = 0; i < 4; i++) av[i] = *(const float4*)(aptr + kt + 4 * i);
            bv0 = *(const float4*)(bptr + (size_t)kt * HH);
            bv1 = *(const float4*)(bptr + (size_t)kt * HH + 4);
        }
#pragma unroll
        for (int k = 0; k < 16; k++) {
            float4 a0 = *(const float4*)&sm.g.As[buf][k][ty * 16];
            float4 a1 = *(const float4*)&sm.g.As[buf][k][ty * 16 + 4];
            float4 a2 = *(const float4*)&sm.g.As[buf][k][ty * 16 + 8];
            float4 a3 = *(const float4*)&sm.g.As[buf][k][ty * 16 + 12];
            ulonglong2 b01 = *(const ulonglong2*)&sm.g.Bs[buf][k][tx * 8];
            ulonglong2 b23 = *(const ulonglong2*)&sm.g.Bs[buf][k][tx * 8 + 4];
            unsigned long long bq[4] = {b01.x, b01.y, b23.x, b23.y};
            float a[16] = {a0.x, a0.y, a0.z, a0.w, a1.x, a1.y, a1.z, a1.w,
                           a2.x, a2.y, a2.z, a2.w, a3.x, a3.y, a3.z, a3.w};
#pragma unroll
            for (int i = 0; i < 16; i++) {
                unsigned long long ai = dup2(a[i]);
#pragma unroll
                for (int q = 0; q < 4; q++)
                    acc2[i][q] = fma2(ai, bq[q], acc2[i][q]);
            }
        }
        if (more) {
            int nb = buf ^ 1;
#pragma unroll
            for (int i = 0; i < 4; i++) {
                sm.g.As[nb][4*i + 0][tid] = av[i].x;
                sm.g.As[nb][4*i + 1][tid] = av[i].y;
                sm.g.As[nb][4*i + 2][tid] = av[i].z;
                sm.g.As[nb][4*i + 3][tid] = av[i].w;
            }
            *(float4*)&sm.g.Bs[nb][ty][tx * 8]     = bv0;
            *(float4*)&sm.g.Bs[nb][ty][tx * 8 + 4] = bv1;
            __syncthreads();
            buf = nb;
        }
    }

    float ss[8] = {0,0,0,0,0,0,0,0}, sc[8] = {0,0,0,0,0,0,0,0};
    float qs[8] = {0,0,0,0,0,0,0,0}, qc[8] = {0,0,0,0,0,0,0,0};
#pragma unroll
    for (int i = 0; i < 16; i++) {
        unsigned long long* p =
            (unsigned long long*)&g_h[(size_t)(bm0 + ty * 16 + i) * HH + bn0 + tx * 8];
        *(ulonglong2*)p       = make_ulonglong2(acc2[i][0], acc2[i][1]);
        *(ulonglong2*)(p + 2) = make_ulonglong2(acc2[i][2], acc2[i][3]);
#pragma unroll
        for (int q = 0; q < 4; q++) {
            float2 v2 = *(float2*)&acc2[i][q];
            kadd(v2.x, ss[2*q],   sc[2*q]);
            kadd(__fmul_rn(v2.x, v2.x), qs[2*q],   qc[2*q]);
            kadd(v2.y, ss[2*q+1], sc[2*q+1]);
            kadd(__fmul_rn(v2.y, v2.y), qs[2*q+1], qc[2*q+1]);
        }
    }
    __syncthreads();
#pragma unroll
    for (int j = 0; j < 8; j++) {
        int col = tx * 8 + j;
        sm.st.s[ty][col]  = ss[j];
        sm.st.c[ty][col]  = sc[j];
        sm.st.q[ty][col]  = qs[j];
        sm.st.cq[ty][col] = qc[j];
    }
    __syncthreads();
    if (tid < 128) {
        double sd = 0, qd = 0;
#pragma unroll
        for (int t = 0; t < 16; t++) {
            sd += (double)sm.st.s[t][tid] - (double)sm.st.c[t][tid];
            qd += (double)sm.st.q[t][tid] - (double)sm.st.cq[t][tid];
        }
        g_part[blockIdx.y][bn0 + tid]      = sd;
        g_part[blockIdx.y][HH + bn0 + tid] = qd;
    }
}

// Widened: 16 blocks x 64 threads. Per-column serial p-loop unchanged
// (one thread per column, p ascending) -> bit-identical fp64 results.
__global__ void k_reduce1() {
    int c = blockIdx.x * 64 + threadIdx.x;
    double s = 0, sq = 0;
    for (int p = 0; p < NPART1; p++) { s += g_part[p][c]; sq += g_part[p][HH + c]; }
    double mu = s / (double)BB;
    double var = sq / (double)BB - mu * mu;
    g_muf[c] = (float)mu;
    g_rf[c]  = (float)(1.0 / sqrt(var + 1e-5));
}

__global__ void k_pack1(const float* __restrict__ gv, const float* __restrict__ bv) {
    int idx = blockIdx.x * 256 + threadIdx.x;
    int c = idx & (HH - 1);
    float h = g_h[idx];
    float z = __fadd_rn(__fmul_rn(__fmul_rn(__fsub_rn(h, g_muf[c]), g_rf[c]), gv[c]), bv[c]);
    unsigned bal = __ballot_sync(0xffffffffu, z > 0.f);
    if ((threadIdx.x & 31) == 0) g_act[idx >> 5] = bal;
}

// ===================================================================
// Fused binary GEMM + noisy_binarize + bit-pack + column-sums (exact int)
// ===================================================================
__global__ __launch_bounds__(256) void k_bgemm_fused(int which, const float* __restrict__ U) {
    __shared__ unsigned As[32][128];
    __shared__ unsigned Ws[32][128];
    __shared__ float lut[27];
    __shared__ unsigned char sbits[128][16];
    __shared__ int icol[128][17];

    const unsigned* __restrict__ Wb = (which == 0) ? g_w2 : g_w3;
    int bn0 = blockIdx.x * 128;
    int bm0 = blockIdx.y * 128;
    int tid = threadIdx.x;
    int ty = tid >> 4, tx = tid & 15;

    if (tid < 27) lut[tid] = g_lutf[tid];

#pragma unroll
    for (int i = 0; i < 4; i++) {
        int p = tid * 4 + i;
        int r = p >> 3, c4 = (p & 7) << 2;
        uint4 av = *(const uint4*)&g_act[(size_t)(bm0 + r) * NW + c4];
        As[c4 + 0][r] = av.x; As[c4 + 1][r] = av.y;
        As[c4 + 2][r] = av.z; As[c4 + 3][r] = av.w;
        uint4 wv = *(const uint4*)&Wb[(size_t)(bn0 + r) * NW + c4];
        Ws[c4 + 0][r] = wv.x; Ws[c4 + 1][r] = wv.y;
        Ws[c4 + 2][r] = wv.z; Ws[c4 + 3][r] = wv.w;
    }
    __syncthreads();

    int acc[8][8];
#pragma unroll
    for (int i = 0; i < 8; i++)
#pragma unroll
        for (int j = 0; j < 8; j++) acc[i][j] = 0;

    for (int w = 0; w < 32; w += 2) {
        unsigned a0[8], b0[8], a1[8], b1[8];
#pragma unroll
        for (int i = 0; i < 8; i++) { a0[i] = As[w][ty * 8 + i]; a1[i] = As[w + 1][ty * 8 + i]; }
#pragma unroll
        for (int j = 0; j < 8; j++) { b0[j] = Ws[w][tx * 8 + j]; b1[j] = Ws[w + 1][tx * 8 + j]; }
#pragma unroll
        for (int i = 0; i < 8; i++)
#pragma unroll
            for (int j = 0; j < 8; j++)
                acc[i][j] += __popc(a0[i] ^ b0[j]) + __popc(a1[i] ^ b1[j]);
    }

    int csum[8];
#pragma unroll
    for (int j = 0; j < 8; j++) csum[j] = 0;
#pragma unroll
    for (int i = 0; i < 8; i++) {
        int rowg = bm0 + ty * 8 + i;
        float4 u0 = *(const float4*)&U[(size_t)rowg * HH + bn0 + tx * 8];
        float4 u1 = *(const float4*)&U[(size_t)rowg * HH + bn0 + tx * 8 + 4];
        float uu[8] = {u0.x, u0.y, u0.z, u0.w, u1.x, u1.y, u1.z, u1.w};
        unsigned byte = 0;
#pragma unroll
        for (int j = 0; j < 8; j++) {
            int cnt = acc[i][j];
            int hs = 512 - cnt;                 // h/2
            int m = (hs < 0) ? -hs : hs;
            if (m > 26) m = 26;
            bool pos = (hs > 0) ^ (uu[j] < lut[m]);
            byte |= (pos ? 1u : 0u) << j;
            csum[j] += pos ? 1 : -1;
        }
        sbits[ty * 8 + i][tx] = (unsigned char)byte;
    }
#pragma unroll
    for (int j = 0; j < 8; j++) icol[tx * 8 + j][ty] = csum[j];
    __syncthreads();

#pragma unroll
    for (int v = 0; v < 2; v++) {
        int wi = tid * 2 + v;
        int row = wi >> 2, w = wi & 3;
        unsigned word = *(const unsigned*)&sbits[row][w * 4];
        g_nv[(size_t)(bm0 + row) * NW + blockIdx.x * 4 + w] = word;
    }
    if (tid < 128) {
        int s = 0;
#pragma unroll
        for (int t = 0; t < 16; t++) s += icol[tid][t];
        g_part[blockIdx.y][bn0 + tid] = (double)s;
    }
}

// ===================================================================
// Parallelized BN-LUT build: 32 blocks x 256 threads, 8 slices/column.
// Partials are EXACT INTEGERS in double -> any association is bit-exact.
// ===================================================================
__global__ void k_lut(const float* __restrict__ gv, const float* __restrict__ bv) {
    __shared__ double sh[8][32];
    int c0 = blockIdx.x * 32;
    int t = threadIdx.x;
    int col = t & 31, slice = t >> 5;        // 8 slices x 32 cols
    double s = 0;
    for (int p = slice; p < NPART; p += 8) s += g_part[p][c0 + col];
    sh[slice][col] = s;
    __syncthreads();
    if (t < 32) {
        double tot = 0;
#pragma unroll
        for (int s2 = 0; s2 < 8; s2++) tot += sh[s2][t];
        int c = c0 + t;
        double mu = tot / (double)BB;
        double r = 1.0 / sqrt(1.0 - mu * mu + 1e-5);
        double zp = (( 1.0 - mu) * r) * (double)gv[c] + (double)bv[c];
        double zm = ((-1.0 - mu) * r) * (double)gv[c] + (double)bv[c];
        unsigned pb = __ballot_sync(0xffffffffu, zp > 0.0);
        unsigned mb = __ballot_sync(0xffffffffu, zm > 0.0);
        if (t == 0) {
            g_sel[blockIdx.x] = pb ^ mb;
            g_mb[blockIdx.x]  = mb;
        }
    }
}

__global__ void k_apply() {
    int i = blockIdx.x * 256 + threadIdx.x;
    int w = i & (NW - 1);
    g_act[i] = (g_nv[i] & g_sel[w]) ^ g_mb[w];
}

__global__ __launch_bounds__(256) void k_out(float* __restrict__ outp) {
    __shared__ unsigned As[256][33];
    __shared__ unsigned W4s[NOUT][NW];
    int r0 = blockIdx.x * 256;
    int t = threadIdx.x;
#pragma unroll
    for (int i = 0; i < 32; i++) {
        int p = t + 256 * i;
        As[p >> 5][p & 31] = g_act[(size_t)r0 * NW + p];
    }
    for (int i = t; i < NOUT * NW; i += 256) ((unsigned*)W4s)[i] = g_w4[i];
    __syncthreads();
#pragma unroll
    for (int o = 0; o < NOUT; o++) {
        int cnt = 0;
#pragma unroll
        for (int w = 0; w < NW; w += 2)
            cnt += __popc(As[t][w] ^ W4s[o][w]) + __popc(As[t][w + 1] ^ W4s[o][w + 1]);
        outp[(size_t)(r0 + t) * NOUT + o] = (float)(HH - 2 * cnt);
    }
}

// ===================================================================
extern "C" void kernel_launch(void* const* d_in, const int* in_sizes, int n_in,
                              void* d_out, int out_size) {
    const float* x  = (const float*)d_in[0];
    const float* u2 = (const float*)d_in[1];
    const float* u3 = (const float*)d_in[2];
    const float* W1 = (const float*)d_in[3];
    const float* W2 = (const float*)d_in[4];
    const float* W3 = (const float*)d_in[5];
    const float* W4 = (const float*)d_in[6];
    const float* g1 = (const float*)d_in[7];
    const float* b1 = (const float*)d_in[8];
    const float* g2 = (const float*)d_in[9];
    const float* b2 = (const float*)d_in[10];
    const float* g3 = (const float*)d_in[11];
    const float* b3 = (const float*)d_in[12];
    float* out = (float*)d_out;

    k_mklut<<<1, 27>>>();
    {
        dim3 tb(32, 8), tg((K1 + 31) / 32, HH / 32);
        k_signW1<<<tg, tb>>>(W1);
    }
    k_packAll<<<(2 * W2_ELEMS + W4_ELEMS + 255) / 256, 256>>>(W2, W3, W4);

    // Layer 1: 256x128 tiles, 256 threads (R13 config) -> grid (8, 64)
    dim3 g1grid(HH / 128, BB / 256);
    k_gemm1<<<g1grid, 256>>>(x);
    k_reduce1<<<HH / 64, 64>>>();
    k_pack1<<<(BB * HH) / 256, 256>>>(g1, b1);

    dim3 ggrid(HH / 128, BB / 128);
    // Layer 2
    k_bgemm_fused<<<ggrid, 256>>>(0, u2);
    k_lut<<<NW, 256>>>(g2, b2);
    k_apply<<<(BB * NW) / 256, 256>>>();

    // Layer 3
    k_bgemm_fused<<<ggrid, 256>>>(1, u3);
    k_lut<<<NW, 256>>>(g3, b3);
    k_apply<<<(BB * NW) / 256, 256>>>();

    // Output layer
    k_out<<<BB / 256, 256>>>(out);
}